// round 1
// baseline (speedup 1.0000x reference)
#include <cuda_runtime.h>
#include <math.h>

// ---------------------------------------------------------------------------
// Problem constants
// ---------------------------------------------------------------------------
#define NB    2
#define NSEG  64
#define HIMG  336
#define HP    24
#define CD    768
#define CM    3072
#define RH    48
#define HID   128
#define P2    (RH*RH)        // 2304 pixels
#define LNEPS 1e-12f

// ---------------------------------------------------------------------------
// Scratch ( __device__ globals; no allocation allowed )
// ---------------------------------------------------------------------------
__device__ float g_means[NB * NSEG * CD];                 // (b, s, c)
__device__ float g_sem  [(size_t)NB * CD * P2];           // (b, c, p)
__device__ float g_h    [(size_t)NB * HID * P2];          // (b, c, p)
__device__ float g_act0 [(size_t)NB * CM * P2];           // (b, c, p)  56.6 MB
__device__ float g_x1   [(size_t)NB * 8 * P2];
__device__ float g_act1 [(size_t)NB * 8 * P2];
__device__ float g_x2   [(size_t)NB * 16 * P2];
__device__ float g_act2 [(size_t)NB * 16 * P2];
__device__ float g_stats[12];                             // [layer][b][{sum,sumsq}]

// ---------------------------------------------------------------------------
__global__ void zero_stats_k() {
    if (threadIdx.x < 12) g_stats[threadIdx.x] = 0.f;
}

// ---------------------------------------------------------------------------
// Per-segment channel means from f_sem at the 24x24 nearest-downsampled segmap.
// grid (64, 2), 256 threads. Each block: one (s, b).
// ---------------------------------------------------------------------------
__global__ void seg_means_k(const float* __restrict__ f_sem,
                            const int*   __restrict__ segmap) {
    const int s = blockIdx.x, b = blockIdx.y;
    __shared__ int segs[HP * HP];
    for (int p = threadIdx.x; p < HP * HP; p += 256) {
        int i = p / HP, j = p % HP;
        int v = segmap[((size_t)b * HIMG + i * 14) * HIMG + j * 14];
        segs[p] = min(max(v, 0), NSEG - 1);
    }
    __syncthreads();
    float acc[3] = {0.f, 0.f, 0.f};
    int cnt = 0;
    for (int p = 0; p < HP * HP; p++) {
        if (segs[p] == s) {
            cnt++;
            int i = p / HP, j = p % HP;
#pragma unroll
            for (int k = 0; k < 3; k++) {
                int c = threadIdx.x + k * 256;
                acc[k] += f_sem[(((size_t)b * CD + c) * HP + i) * HP + j];
            }
        }
    }
    float inv = cnt > 0 ? 1.0f / (float)cnt : 0.0f;
#pragma unroll
    for (int k = 0; k < 3; k++) {
        int c = threadIdx.x + k * 256;
        g_means[((size_t)b * NSEG + s) * CD + c] = acc[k] * inv;
    }
}

// ---------------------------------------------------------------------------
// Fused paint + antialiased bilinear resize (336 -> 48).
// For each output pixel: accumulate per-segment weights over the 15x15 tap
// window of the (normalized) separable triangle kernel, then mix means.
// grid (48, 48, 2), 256 threads.
// ---------------------------------------------------------------------------
__global__ void paint_resize_k(const int* __restrict__ segmap) {
    const int X = blockIdx.x, Y = blockIdx.y, b = blockIdx.z;
    const int t = threadIdx.x;
    __shared__ float wseg[NSEG];
    __shared__ float wy[15], wx[15];

    if (t < NSEG) wseg[t] = 0.f;
    if (t == 0) {
        float sf = 7.0f * Y + 3.0f, norm = 0.f;
        for (int k = 0; k < 15; k++) {
            int y = 7 * Y - 4 + k;
            float w = (y >= 0 && y < HIMG)
                        ? fmaxf(0.f, 1.f - fabsf((float)y - sf) * (1.f / 7.f)) : 0.f;
            wy[k] = w; norm += w;
        }
        float inv = 1.f / norm;
        for (int k = 0; k < 15; k++) wy[k] *= inv;
    }
    if (t == 1) {
        float sf = 7.0f * X + 3.0f, norm = 0.f;
        for (int k = 0; k < 15; k++) {
            int x = 7 * X - 4 + k;
            float w = (x >= 0 && x < HIMG)
                        ? fmaxf(0.f, 1.f - fabsf((float)x - sf) * (1.f / 7.f)) : 0.f;
            wx[k] = w; norm += w;
        }
        float inv = 1.f / norm;
        for (int k = 0; k < 15; k++) wx[k] *= inv;
    }
    __syncthreads();

    if (t < 225) {
        int ty = t / 15, tx = t % 15;
        int y = 7 * Y - 4 + ty, x = 7 * X - 4 + tx;
        if (y >= 0 && y < HIMG && x >= 0 && x < HIMG) {
            float w = wy[ty] * wx[tx];
            if (w != 0.f) {
                int seg = segmap[((size_t)b * HIMG + y) * HIMG + x];
                seg = min(max(seg, 0), NSEG - 1);
                atomicAdd(&wseg[seg], w);
            }
        }
    }
    __syncthreads();

    const float* M = g_means + (size_t)b * NSEG * CD;
    const int p = Y * RH + X;
    for (int c = t; c < CD; c += 256) {
        float a = 0.f;
#pragma unroll 16
        for (int s = 0; s < NSEG; s++) a = fmaf(wseg[s], M[(size_t)s * CD + c], a);
        g_sem[((size_t)b * CD + c) * P2 + p] = a;
    }
}

// ---------------------------------------------------------------------------
// Layernorm statistics: per-batch sum and sum-of-squares via atomics.
// grid (nBlocksX, 2), 256 threads.
// ---------------------------------------------------------------------------
__global__ void ln_stats_k(const float* __restrict__ x, int nPerB, int layer) {
    const int b = blockIdx.y;
    const float* xb = x + (size_t)b * nPerB;
    float s = 0.f, s2 = 0.f;
    for (long i = (long)blockIdx.x * blockDim.x + threadIdx.x; i < nPerB;
         i += (long)gridDim.x * blockDim.x) {
        float v = xb[i];
        s += v;
        s2 = fmaf(v, v, s2);
    }
#pragma unroll
    for (int o = 16; o; o >>= 1) {
        s  += __shfl_down_sync(0xffffffffu, s, o);
        s2 += __shfl_down_sync(0xffffffffu, s2, o);
    }
    __shared__ float sh[32][2];
    int w = threadIdx.x >> 5, l = threadIdx.x & 31;
    if (l == 0) { sh[w][0] = s; sh[w][1] = s2; }
    __syncthreads();
    if (threadIdx.x < 32) {
        int nw = blockDim.x >> 5;
        s  = (threadIdx.x < nw) ? sh[threadIdx.x][0] : 0.f;
        s2 = (threadIdx.x < nw) ? sh[threadIdx.x][1] : 0.f;
#pragma unroll
        for (int o = 16; o; o >>= 1) {
            s  += __shfl_down_sync(0xffffffffu, s, o);
            s2 += __shfl_down_sync(0xffffffffu, s2, o);
        }
        if (threadIdx.x == 0) {
            atomicAdd(&g_stats[layer * 4 + b * 2 + 0], s);
            atomicAdd(&g_stats[layer * 4 + b * 2 + 1], s2);
        }
    }
}

// ---------------------------------------------------------------------------
// Direct 3x3 conv (pad 1) + bias + relu.  Tiles: 16x16 spatial, 8 couts/block.
// grid (9, Cout/8, 2), 256 threads.
// ---------------------------------------------------------------------------
__global__ void conv3x3_relu_k(const float* __restrict__ in,
                               const float* __restrict__ wt,
                               const float* __restrict__ bias,
                               float* __restrict__ out, int Cin) {
    const int tile = blockIdx.x;
    const int ty0 = (tile / 3) * 16, tx0 = (tile % 3) * 16;
    const int co0 = blockIdx.y * 8;
    const int Cout = gridDim.y * 8;
    const int b = blockIdx.z;
    const int t = threadIdx.x;
    const int py = t >> 4, px = t & 15;

    __shared__ float sin_s[8][18 * 18];
    __shared__ float sw[8][8][9];

    float acc[8];
#pragma unroll
    for (int i = 0; i < 8; i++) acc[i] = 0.f;

    const size_t inB = (size_t)b * Cin * P2;
    for (int ci0 = 0; ci0 < Cin; ci0 += 8) {
        for (int idx = t; idx < 8 * 324; idx += 256) {
            int c = idx / 324, q = idx - c * 324;
            int iy = ty0 + q / 18 - 1, ix = tx0 + (q % 18) - 1;
            float v = 0.f;
            if (iy >= 0 && iy < RH && ix >= 0 && ix < RH)
                v = in[inB + (size_t)(ci0 + c) * P2 + iy * RH + ix];
            sin_s[c][q] = v;
        }
        for (int idx = t; idx < 576; idx += 256) {
            int co = idx / 72, r = idx - co * 72;
            sw[co][r / 9][r % 9] =
                wt[((size_t)(co0 + co) * Cin + ci0 + r / 9) * 9 + (r % 9)];
        }
        __syncthreads();
#pragma unroll
        for (int ci = 0; ci < 8; ci++) {
            float v[9];
#pragma unroll
            for (int ky = 0; ky < 3; ky++)
#pragma unroll
                for (int kx = 0; kx < 3; kx++)
                    v[ky * 3 + kx] = sin_s[ci][(py + ky) * 18 + px + kx];
#pragma unroll
            for (int co = 0; co < 8; co++) {
                float a = acc[co];
#pragma unroll
                for (int k = 0; k < 9; k++) a = fmaf(v[k], sw[co][ci][k], a);
                acc[co] = a;
            }
        }
        __syncthreads();
    }
    const int p = (ty0 + py) * RH + tx0 + px;
#pragma unroll
    for (int co = 0; co < 8; co++) {
        float r = acc[co] + bias[co0 + co];
        out[((size_t)b * Cout + co0 + co) * P2 + p] = fmaxf(r, 0.f);
    }
}

// ---------------------------------------------------------------------------
// Fused gamma/beta 3x3 convs (Cin=128) + layernorm apply:
//   act = (x - mean)*rstd * (1 + gamma) + beta
// grid (9, nf/8, 2), 256 threads.
// ---------------------------------------------------------------------------
__global__ void spade_apply_k(const float* __restrict__ hin,
                              const float* __restrict__ wg, const float* __restrict__ bg,
                              const float* __restrict__ wb, const float* __restrict__ bb,
                              const float* __restrict__ x, float* __restrict__ act,
                              int layer, float invN) {
    const int tile = blockIdx.x;
    const int ty0 = (tile / 3) * 16, tx0 = (tile % 3) * 16;
    const int co0 = blockIdx.y * 8;
    const int nf = gridDim.y * 8;
    const int b = blockIdx.z;
    const int t = threadIdx.x;
    const int py = t >> 4, px = t & 15;

    __shared__ float sin_s[8][18 * 18];
    __shared__ float swg[8][8][9];
    __shared__ float swb[8][8][9];

    float accg[8], accb[8];
#pragma unroll
    for (int i = 0; i < 8; i++) { accg[i] = 0.f; accb[i] = 0.f; }

    const size_t inB = (size_t)b * HID * P2;
    for (int ci0 = 0; ci0 < HID; ci0 += 8) {
        for (int idx = t; idx < 8 * 324; idx += 256) {
            int c = idx / 324, q = idx - c * 324;
            int iy = ty0 + q / 18 - 1, ix = tx0 + (q % 18) - 1;
            float v = 0.f;
            if (iy >= 0 && iy < RH && ix >= 0 && ix < RH)
                v = hin[inB + (size_t)(ci0 + c) * P2 + iy * RH + ix];
            sin_s[c][q] = v;
        }
        for (int idx = t; idx < 576; idx += 256) {
            int co = idx / 72, r = idx - co * 72;
            size_t wi = ((size_t)(co0 + co) * HID + ci0 + r / 9) * 9 + (r % 9);
            swg[co][r / 9][r % 9] = wg[wi];
            swb[co][r / 9][r % 9] = wb[wi];
        }
        __syncthreads();
#pragma unroll
        for (int ci = 0; ci < 8; ci++) {
            float v[9];
#pragma unroll
            for (int ky = 0; ky < 3; ky++)
#pragma unroll
                for (int kx = 0; kx < 3; kx++)
                    v[ky * 3 + kx] = sin_s[ci][(py + ky) * 18 + px + kx];
#pragma unroll
            for (int co = 0; co < 8; co++) {
                float ag = accg[co], ab = accb[co];
#pragma unroll
                for (int k = 0; k < 9; k++) {
                    ag = fmaf(v[k], swg[co][ci][k], ag);
                    ab = fmaf(v[k], swb[co][ci][k], ab);
                }
                accg[co] = ag; accb[co] = ab;
            }
        }
        __syncthreads();
    }

    const float sum   = g_stats[layer * 4 + b * 2 + 0];
    const float sumsq = g_stats[layer * 4 + b * 2 + 1];
    const float mean  = sum * invN;
    const float var   = sumsq * invN - mean * mean;
    const float rstd  = rsqrtf(var + LNEPS);

    const int p = (ty0 + py) * RH + tx0 + px;
#pragma unroll
    for (int co = 0; co < 8; co++) {
        int c = co0 + co;
        float g  = accg[co] + bg[c];
        float be = accb[co] + bb[c];
        float xv = x[((size_t)b * nf + c) * P2 + p];
        float xn = (xv - mean) * rstd;
        act[((size_t)b * nf + c) * P2 + p] = fmaf(xn, 1.f + g, be);
    }
}

// ---------------------------------------------------------------------------
// 1x1 conv + softplus.  grid (9, 2), 256 threads; one pixel per thread.
// ---------------------------------------------------------------------------
__device__ __forceinline__ float softplus_f(float z) {
    return fmaxf(z, 0.f) + log1pf(expf(-fabsf(z)));
}

template <int COUT>
__global__ void conv1x1_softplus_k(const float* __restrict__ act,
                                   const float* __restrict__ w,
                                   const float* __restrict__ bias,
                                   float* __restrict__ out, int Cin) {
    const int p = blockIdx.x * blockDim.x + threadIdx.x;
    const int b = blockIdx.y;
    float acc[COUT];
#pragma unroll
    for (int j = 0; j < COUT; j++) acc[j] = 0.f;
    const float* ab = act + (size_t)b * Cin * P2 + p;
    for (int c = 0; c < Cin; c++) {
        float v = ab[(size_t)c * P2];
#pragma unroll
        for (int j = 0; j < COUT; j++)
            acc[j] = fmaf(__ldg(&w[(size_t)j * Cin + c]), v, acc[j]);
    }
#pragma unroll
    for (int j = 0; j < COUT; j++)
        out[((size_t)b * COUT + j) * P2 + p] = softplus_f(acc[j] + bias[j]);
}

// ---------------------------------------------------------------------------
static float* sym_ptr(const void* sym) {
    void* p = nullptr;
    cudaGetSymbolAddress(&p, sym);
    return (float*)p;
}

extern "C" void kernel_launch(void* const* d_in, const int* in_sizes, int n_in,
                              void* d_out, int out_size) {
    const float* x_main = (const float*)d_in[0];
    const float* f_sem  = (const float*)d_in[1];
    const int*   segmap = (const int*)  d_in[2];
    const float* ws[3] = {(const float*)d_in[3],  (const float*)d_in[9],  (const float*)d_in[15]};
    const float* bs[3] = {(const float*)d_in[4],  (const float*)d_in[10], (const float*)d_in[16]};
    const float* wg[3] = {(const float*)d_in[5],  (const float*)d_in[11], (const float*)d_in[17]};
    const float* bg[3] = {(const float*)d_in[6],  (const float*)d_in[12], (const float*)d_in[18]};
    const float* wb[3] = {(const float*)d_in[7],  (const float*)d_in[13], (const float*)d_in[19]};
    const float* bb[3] = {(const float*)d_in[8],  (const float*)d_in[14], (const float*)d_in[20]};
    const float* w1x[3] = {(const float*)d_in[21], (const float*)d_in[23], (const float*)d_in[25]};
    const float* b1x[3] = {(const float*)d_in[22], (const float*)d_in[24], (const float*)d_in[26]};
    float* out = (float*)d_out;

    float* p_sem  = sym_ptr(g_sem);
    float* p_h    = sym_ptr(g_h);
    float* p_act0 = sym_ptr(g_act0);
    float* p_x1   = sym_ptr(g_x1);
    float* p_act1 = sym_ptr(g_act1);
    float* p_x2   = sym_ptr(g_x2);
    float* p_act2 = sym_ptr(g_act2);

    zero_stats_k<<<1, 32>>>();
    seg_means_k<<<dim3(NSEG, NB), 256>>>(f_sem, segmap);
    paint_resize_k<<<dim3(RH, RH, NB), 256>>>(segmap);

    // ---- layer 0 (x = x_main, nf = 3072) ----
    ln_stats_k<<<dim3(64, NB), 256>>>(x_main, CM * P2, 0);
    conv3x3_relu_k<<<dim3(9, HID / 8, NB), 256>>>(p_sem, ws[0], bs[0], p_h, CD);
    spade_apply_k<<<dim3(9, CM / 8, NB), 256>>>(p_h, wg[0], bg[0], wb[0], bb[0],
                                                x_main, p_act0, 0, 1.f / (CM * P2));
    conv1x1_softplus_k<8><<<dim3(9, NB), 256>>>(p_act0, w1x[0], b1x[0], p_x1, CM);

    // ---- layer 1 (x = x1 (8ch), nf = 8) ----
    ln_stats_k<<<dim3(2, NB), 256>>>(p_x1, 8 * P2, 1);
    conv3x3_relu_k<<<dim3(9, HID / 8, NB), 256>>>(p_sem, ws[1], bs[1], p_h, CD);
    spade_apply_k<<<dim3(9, 1, NB), 256>>>(p_h, wg[1], bg[1], wb[1], bb[1],
                                           p_x1, p_act1, 1, 1.f / (8 * P2));
    conv1x1_softplus_k<16><<<dim3(9, NB), 256>>>(p_act1, w1x[1], b1x[1], p_x2, 8);

    // ---- layer 2 (x = x2 (16ch), nf = 16) ----
    ln_stats_k<<<dim3(2, NB), 256>>>(p_x2, 16 * P2, 2);
    conv3x3_relu_k<<<dim3(9, HID / 8, NB), 256>>>(p_sem, ws[2], bs[2], p_h, CD);
    spade_apply_k<<<dim3(9, 2, NB), 256>>>(p_h, wg[2], bg[2], wb[2], bb[2],
                                           p_x2, p_act2, 2, 1.f / (16 * P2));
    conv1x1_softplus_k<1><<<dim3(9, NB), 256>>>(p_act2, w1x[2], b1x[2], out, 16);
}

// round 2
// speedup vs baseline: 1.0398x; 1.0398x over previous
#include <cuda_runtime.h>
#include <math.h>

// ---------------------------------------------------------------------------
// Problem constants
// ---------------------------------------------------------------------------
#define NB    2
#define NSEG  64
#define HIMG  336
#define HP    24
#define CD    768
#define CM    3072
#define RH    48
#define HID   128
#define P2    (RH*RH)        // 2304 pixels
#define LNEPS 1e-12f

// ---------------------------------------------------------------------------
// Scratch ( __device__ globals; no allocation allowed )
// ---------------------------------------------------------------------------
__device__ float g_means[NB * NSEG * CD];                 // (b, s, c)
__device__ float g_sem  [(size_t)NB * CD * P2];           // (b, c, p)
__device__ float g_h    [(size_t)NB * HID * P2];          // (b, c, p)
__device__ float g_act0 [(size_t)NB * CM * P2];           // (b, c, p)  56.6 MB
__device__ float g_x1   [(size_t)NB * 8 * P2];
__device__ float g_act1 [(size_t)NB * 8 * P2];
__device__ float g_x2   [(size_t)NB * 16 * P2];
__device__ float g_act2 [(size_t)NB * 16 * P2];
__device__ float g_stats[12];                             // [layer][b][{sum,sumsq}]

// ---------------------------------------------------------------------------
__global__ void zero_stats_k() {
    if (threadIdx.x < 12) g_stats[threadIdx.x] = 0.f;
}

// ---------------------------------------------------------------------------
// Per-segment channel means from f_sem at the 24x24 nearest-downsampled segmap.
// grid (64, 2), 256 threads. Each block: one (s, b).
// ---------------------------------------------------------------------------
__global__ void seg_means_k(const float* __restrict__ f_sem,
                            const int*   __restrict__ segmap) {
    const int s = blockIdx.x, b = blockIdx.y;
    __shared__ int segs[HP * HP];
    for (int p = threadIdx.x; p < HP * HP; p += 256) {
        int i = p / HP, j = p % HP;
        int v = segmap[((size_t)b * HIMG + i * 14) * HIMG + j * 14];
        segs[p] = min(max(v, 0), NSEG - 1);
    }
    __syncthreads();
    float acc[3] = {0.f, 0.f, 0.f};
    int cnt = 0;
    for (int p = 0; p < HP * HP; p++) {
        if (segs[p] == s) {
            cnt++;
            int i = p / HP, j = p % HP;
#pragma unroll
            for (int k = 0; k < 3; k++) {
                int c = threadIdx.x + k * 256;
                acc[k] += f_sem[(((size_t)b * CD + c) * HP + i) * HP + j];
            }
        }
    }
    float inv = cnt > 0 ? 1.0f / (float)cnt : 0.0f;
#pragma unroll
    for (int k = 0; k < 3; k++) {
        int c = threadIdx.x + k * 256;
        g_means[((size_t)b * NSEG + s) * CD + c] = acc[k] * inv;
    }
}

// ---------------------------------------------------------------------------
// Fused paint + antialiased bilinear resize (336 -> 48).
// For each output pixel: accumulate per-segment weights over the 15x15 tap
// window of the (normalized) separable triangle kernel, then mix means.
// grid (48, 48, 2), 256 threads.
// ---------------------------------------------------------------------------
__global__ void paint_resize_k(const int* __restrict__ segmap) {
    const int X = blockIdx.x, Y = blockIdx.y, b = blockIdx.z;
    const int t = threadIdx.x;
    __shared__ float wseg[NSEG];
    __shared__ float wy[15], wx[15];

    if (t < NSEG) wseg[t] = 0.f;
    if (t == 0) {
        float sf = 7.0f * Y + 3.0f, norm = 0.f;
        for (int k = 0; k < 15; k++) {
            int y = 7 * Y - 4 + k;
            float w = (y >= 0 && y < HIMG)
                        ? fmaxf(0.f, 1.f - fabsf((float)y - sf) * (1.f / 7.f)) : 0.f;
            wy[k] = w; norm += w;
        }
        float inv = 1.f / norm;
        for (int k = 0; k < 15; k++) wy[k] *= inv;
    }
    if (t == 1) {
        float sf = 7.0f * X + 3.0f, norm = 0.f;
        for (int k = 0; k < 15; k++) {
            int x = 7 * X - 4 + k;
            float w = (x >= 0 && x < HIMG)
                        ? fmaxf(0.f, 1.f - fabsf((float)x - sf) * (1.f / 7.f)) : 0.f;
            wx[k] = w; norm += w;
        }
        float inv = 1.f / norm;
        for (int k = 0; k < 15; k++) wx[k] *= inv;
    }
    __syncthreads();

    if (t < 225) {
        int ty = t / 15, tx = t % 15;
        int y = 7 * Y - 4 + ty, x = 7 * X - 4 + tx;
        if (y >= 0 && y < HIMG && x >= 0 && x < HIMG) {
            float w = wy[ty] * wx[tx];
            if (w != 0.f) {
                int seg = segmap[((size_t)b * HIMG + y) * HIMG + x];
                seg = min(max(seg, 0), NSEG - 1);
                atomicAdd(&wseg[seg], w);
            }
        }
    }
    __syncthreads();

    const float* M = g_means + (size_t)b * NSEG * CD;
    const int p = Y * RH + X;
    for (int c = t; c < CD; c += 256) {
        float a = 0.f;
#pragma unroll 16
        for (int s = 0; s < NSEG; s++) a = fmaf(wseg[s], M[(size_t)s * CD + c], a);
        g_sem[((size_t)b * CD + c) * P2 + p] = a;
    }
}

// ---------------------------------------------------------------------------
// Layernorm statistics: per-batch sum and sum-of-squares via atomics.
// grid (nBlocksX, 2), 256 threads.
// ---------------------------------------------------------------------------
__global__ void ln_stats_k(const float* __restrict__ x, int nPerB, int layer) {
    const int b = blockIdx.y;
    const float* xb = x + (size_t)b * nPerB;
    float s = 0.f, s2 = 0.f;
    for (long i = (long)blockIdx.x * blockDim.x + threadIdx.x; i < nPerB;
         i += (long)gridDim.x * blockDim.x) {
        float v = xb[i];
        s += v;
        s2 = fmaf(v, v, s2);
    }
#pragma unroll
    for (int o = 16; o; o >>= 1) {
        s  += __shfl_down_sync(0xffffffffu, s, o);
        s2 += __shfl_down_sync(0xffffffffu, s2, o);
    }
    __shared__ float sh[32][2];
    int w = threadIdx.x >> 5, l = threadIdx.x & 31;
    if (l == 0) { sh[w][0] = s; sh[w][1] = s2; }
    __syncthreads();
    if (threadIdx.x < 32) {
        int nw = blockDim.x >> 5;
        s  = (threadIdx.x < nw) ? sh[threadIdx.x][0] : 0.f;
        s2 = (threadIdx.x < nw) ? sh[threadIdx.x][1] : 0.f;
#pragma unroll
        for (int o = 16; o; o >>= 1) {
            s  += __shfl_down_sync(0xffffffffu, s, o);
            s2 += __shfl_down_sync(0xffffffffu, s2, o);
        }
        if (threadIdx.x == 0) {
            atomicAdd(&g_stats[layer * 4 + b * 2 + 0], s);
            atomicAdd(&g_stats[layer * 4 + b * 2 + 1], s2);
        }
    }
}

// ---------------------------------------------------------------------------
// Direct 3x3 conv (pad 1) + bias + relu.  Tiles: 16x16 spatial, 8 couts/block.
// grid (9, Cout/8, 2), 256 threads.
// ---------------------------------------------------------------------------
__global__ void conv3x3_relu_k(const float* __restrict__ in,
                               const float* __restrict__ wt,
                               const float* __restrict__ bias,
                               float* __restrict__ out, int Cin) {
    const int tile = blockIdx.x;
    const int ty0 = (tile / 3) * 16, tx0 = (tile % 3) * 16;
    const int co0 = blockIdx.y * 8;
    const int Cout = gridDim.y * 8;
    const int b = blockIdx.z;
    const int t = threadIdx.x;
    const int py = t >> 4, px = t & 15;

    __shared__ float sin_s[8][18 * 18];
    __shared__ float sw[8][8][9];

    float acc[8];
#pragma unroll
    for (int i = 0; i < 8; i++) acc[i] = 0.f;

    const size_t inB = (size_t)b * Cin * P2;
    for (int ci0 = 0; ci0 < Cin; ci0 += 8) {
        for (int idx = t; idx < 8 * 324; idx += 256) {
            int c = idx / 324, q = idx - c * 324;
            int iy = ty0 + q / 18 - 1, ix = tx0 + (q % 18) - 1;
            float v = 0.f;
            if (iy >= 0 && iy < RH && ix >= 0 && ix < RH)
                v = in[inB + (size_t)(ci0 + c) * P2 + iy * RH + ix];
            sin_s[c][q] = v;
        }
        for (int idx = t; idx < 576; idx += 256) {
            int co = idx / 72, r = idx - co * 72;
            sw[co][r / 9][r % 9] =
                wt[((size_t)(co0 + co) * Cin + ci0 + r / 9) * 9 + (r % 9)];
        }
        __syncthreads();
#pragma unroll
        for (int ci = 0; ci < 8; ci++) {
            float v[9];
#pragma unroll
            for (int ky = 0; ky < 3; ky++)
#pragma unroll
                for (int kx = 0; kx < 3; kx++)
                    v[ky * 3 + kx] = sin_s[ci][(py + ky) * 18 + px + kx];
#pragma unroll
            for (int co = 0; co < 8; co++) {
                float a = acc[co];
#pragma unroll
                for (int k = 0; k < 9; k++) a = fmaf(v[k], sw[co][ci][k], a);
                acc[co] = a;
            }
        }
        __syncthreads();
    }
    const int p = (ty0 + py) * RH + tx0 + px;
#pragma unroll
    for (int co = 0; co < 8; co++) {
        float r = acc[co] + bias[co0 + co];
        out[((size_t)b * Cout + co0 + co) * P2 + p] = fmaxf(r, 0.f);
    }
}

// ---------------------------------------------------------------------------
// Fused gamma/beta 3x3 convs (Cin=128) + layernorm apply:
//   act = (x - mean)*rstd * (1 + gamma) + beta
// grid (9, nf/8, 2), 256 threads.
// ---------------------------------------------------------------------------
__global__ void spade_apply_k(const float* __restrict__ hin,
                              const float* __restrict__ wg, const float* __restrict__ bg,
                              const float* __restrict__ wb, const float* __restrict__ bb,
                              const float* __restrict__ x, float* __restrict__ act,
                              int layer, float invN) {
    const int tile = blockIdx.x;
    const int ty0 = (tile / 3) * 16, tx0 = (tile % 3) * 16;
    const int co0 = blockIdx.y * 8;
    const int nf = gridDim.y * 8;
    const int b = blockIdx.z;
    const int t = threadIdx.x;
    const int py = t >> 4, px = t & 15;

    __shared__ float sin_s[8][18 * 18];
    __shared__ float swg[8][8][9];
    __shared__ float swb[8][8][9];

    float accg[8], accb[8];
#pragma unroll
    for (int i = 0; i < 8; i++) { accg[i] = 0.f; accb[i] = 0.f; }

    const size_t inB = (size_t)b * HID * P2;
    for (int ci0 = 0; ci0 < HID; ci0 += 8) {
        for (int idx = t; idx < 8 * 324; idx += 256) {
            int c = idx / 324, q = idx - c * 324;
            int iy = ty0 + q / 18 - 1, ix = tx0 + (q % 18) - 1;
            float v = 0.f;
            if (iy >= 0 && iy < RH && ix >= 0 && ix < RH)
                v = hin[inB + (size_t)(ci0 + c) * P2 + iy * RH + ix];
            sin_s[c][q] = v;
        }
        for (int idx = t; idx < 576; idx += 256) {
            int co = idx / 72, r = idx - co * 72;
            size_t wi = ((size_t)(co0 + co) * HID + ci0 + r / 9) * 9 + (r % 9);
            swg[co][r / 9][r % 9] = wg[wi];
            swb[co][r / 9][r % 9] = wb[wi];
        }
        __syncthreads();
#pragma unroll
        for (int ci = 0; ci < 8; ci++) {
            float v[9];
#pragma unroll
            for (int ky = 0; ky < 3; ky++)
#pragma unroll
                for (int kx = 0; kx < 3; kx++)
                    v[ky * 3 + kx] = sin_s[ci][(py + ky) * 18 + px + kx];
#pragma unroll
            for (int co = 0; co < 8; co++) {
                float ag = accg[co], ab = accb[co];
#pragma unroll
                for (int k = 0; k < 9; k++) {
                    ag = fmaf(v[k], swg[co][ci][k], ag);
                    ab = fmaf(v[k], swb[co][ci][k], ab);
                }
                accg[co] = ag; accb[co] = ab;
            }
        }
        __syncthreads();
    }

    const float sum   = g_stats[layer * 4 + b * 2 + 0];
    const float sumsq = g_stats[layer * 4 + b * 2 + 1];
    const float mean  = sum * invN;
    const float var   = sumsq * invN - mean * mean;
    const float rstd  = rsqrtf(var + LNEPS);

    const int p = (ty0 + py) * RH + tx0 + px;
#pragma unroll
    for (int co = 0; co < 8; co++) {
        int c = co0 + co;
        float g  = accg[co] + bg[c];
        float be = accb[co] + bb[c];
        float xv = x[((size_t)b * nf + c) * P2 + p];
        float xn = (xv - mean) * rstd;
        act[((size_t)b * nf + c) * P2 + p] = fmaf(xn, 1.f + g, be);
    }
}

// ---------------------------------------------------------------------------
// 1x1 conv + softplus.  grid (9, 2), 256 threads; one pixel per thread.
// ---------------------------------------------------------------------------
__device__ __forceinline__ float softplus_f(float z) {
    return fmaxf(z, 0.f) + log1pf(expf(-fabsf(z)));
}

template <int COUT>
__global__ void conv1x1_softplus_k(const float* __restrict__ act,
                                   const float* __restrict__ w,
                                   const float* __restrict__ bias,
                                   float* __restrict__ out, int Cin) {
    const int p = blockIdx.x * blockDim.x + threadIdx.x;
    const int b = blockIdx.y;
    float acc[COUT];
#pragma unroll
    for (int j = 0; j < COUT; j++) acc[j] = 0.f;
    const float* ab = act + (size_t)b * Cin * P2 + p;
    for (int c = 0; c < Cin; c++) {
        float v = ab[(size_t)c * P2];
#pragma unroll
        for (int j = 0; j < COUT; j++)
            acc[j] = fmaf(__ldg(&w[(size_t)j * Cin + c]), v, acc[j]);
    }
#pragma unroll
    for (int j = 0; j < COUT; j++)
        out[((size_t)b * COUT + j) * P2 + p] = softplus_f(acc[j] + bias[j]);
}

// ---------------------------------------------------------------------------
static float* sym_ptr(const void* sym) {
    void* p = nullptr;
    cudaGetSymbolAddress(&p, sym);
    return (float*)p;
}

extern "C" void kernel_launch(void* const* d_in, const int* in_sizes, int n_in,
                              void* d_out, int out_size) {
    const float* x_main = (const float*)d_in[0];
    const float* f_sem  = (const float*)d_in[1];
    const int*   segmap = (const int*)  d_in[2];
    const float* ws[3] = {(const float*)d_in[3],  (const float*)d_in[9],  (const float*)d_in[15]};
    const float* bs[3] = {(const float*)d_in[4],  (const float*)d_in[10], (const float*)d_in[16]};
    const float* wg[3] = {(const float*)d_in[5],  (const float*)d_in[11], (const float*)d_in[17]};
    const float* bg[3] = {(const float*)d_in[6],  (const float*)d_in[12], (const float*)d_in[18]};
    const float* wb[3] = {(const float*)d_in[7],  (const float*)d_in[13], (const float*)d_in[19]};
    const float* bb[3] = {(const float*)d_in[8],  (const float*)d_in[14], (const float*)d_in[20]};
    const float* w1x[3] = {(const float*)d_in[21], (const float*)d_in[23], (const float*)d_in[25]};
    const float* b1x[3] = {(const float*)d_in[22], (const float*)d_in[24], (const float*)d_in[26]};
    float* out = (float*)d_out;

    float* p_sem  = sym_ptr(g_sem);
    float* p_h    = sym_ptr(g_h);
    float* p_act0 = sym_ptr(g_act0);
    float* p_x1   = sym_ptr(g_x1);
    float* p_act1 = sym_ptr(g_act1);
    float* p_x2   = sym_ptr(g_x2);
    float* p_act2 = sym_ptr(g_act2);

    zero_stats_k<<<1, 32>>>();
    seg_means_k<<<dim3(NSEG, NB), 256>>>(f_sem, segmap);
    paint_resize_k<<<dim3(RH, RH, NB), 256>>>(segmap);

    // ---- layer 0 (x = x_main, nf = 3072) ----
    ln_stats_k<<<dim3(64, NB), 256>>>(x_main, CM * P2, 0);
    conv3x3_relu_k<<<dim3(9, HID / 8, NB), 256>>>(p_sem, ws[0], bs[0], p_h, CD);
    spade_apply_k<<<dim3(9, CM / 8, NB), 256>>>(p_h, wg[0], bg[0], wb[0], bb[0],
                                                x_main, p_act0, 0, 1.f / (CM * P2));
    conv1x1_softplus_k<8><<<dim3(9, NB), 256>>>(p_act0, w1x[0], b1x[0], p_x1, CM);

    // ---- layer 1 (x = x1 (8ch), nf = 8) ----
    ln_stats_k<<<dim3(2, NB), 256>>>(p_x1, 8 * P2, 1);
    conv3x3_relu_k<<<dim3(9, HID / 8, NB), 256>>>(p_sem, ws[1], bs[1], p_h, CD);
    spade_apply_k<<<dim3(9, 1, NB), 256>>>(p_h, wg[1], bg[1], wb[1], bb[1],
                                           p_x1, p_act1, 1, 1.f / (8 * P2));
    conv1x1_softplus_k<16><<<dim3(9, NB), 256>>>(p_act1, w1x[1], b1x[1], p_x2, 8);

    // ---- layer 2 (x = x2 (16ch), nf = 16) ----
    ln_stats_k<<<dim3(2, NB), 256>>>(p_x2, 16 * P2, 2);
    conv3x3_relu_k<<<dim3(9, HID / 8, NB), 256>>>(p_sem, ws[2], bs[2], p_h, CD);
    spade_apply_k<<<dim3(9, 2, NB), 256>>>(p_h, wg[2], bg[2], wb[2], bb[2],
                                           p_x2, p_act2, 2, 1.f / (16 * P2));
    conv1x1_softplus_k<1><<<dim3(9, NB), 256>>>(p_act2, w1x[2], b1x[2], out, 16);
}

// round 3
// speedup vs baseline: 1.3112x; 1.2610x over previous
#include <cuda_runtime.h>
#include <math.h>

#define NB 2
#define NSEG 64
#define HIMG 336
#define HP 24
#define CD 768
#define CM 3072
#define RH 48
#define HID 128
#define P2 2304
#define LNEPS 1e-12f
#define CI 8
#define WSTR 100  // per-cout weight slab stride in smem (CI*12+4)

__device__ float g_means[NB * NSEG * CD];
__device__ float g_sem[(size_t)NB * CD * P2];
__device__ float g_h[(size_t)3 * NB * HID * P2];
__device__ float g_act0[(size_t)NB * CM * P2];
__device__ float g_x1[NB * 8 * P2];
__device__ float g_act1[NB * 8 * P2];
__device__ float g_x2[NB * 16 * P2];
__device__ float g_act2[NB * 16 * P2];
__device__ float g_stats[12];

__global__ void zero_stats_k() {
    if (threadIdx.x < 12) g_stats[threadIdx.x] = 0.f;
}

// ---------------- per-segment channel means (24x24 nearest segmap) ----------
__global__ void seg_means_k(const float* __restrict__ f_sem,
                            const int* __restrict__ segmap) {
    const int s = blockIdx.x, b = blockIdx.y;
    __shared__ int segs[HP * HP];
    for (int p = threadIdx.x; p < HP * HP; p += 256) {
        int i = p / HP, j = p % HP;
        int v = segmap[((size_t)b * HIMG + i * 14) * HIMG + j * 14];
        segs[p] = min(max(v, 0), NSEG - 1);
    }
    __syncthreads();
    float acc[3] = {0.f, 0.f, 0.f};
    int cnt = 0;
    for (int p = 0; p < HP * HP; p++) {
        if (segs[p] == s) {
            cnt++;
            int i = p / HP, j = p % HP;
#pragma unroll
            for (int k = 0; k < 3; k++) {
                int c = threadIdx.x + k * 256;
                acc[k] += f_sem[(((size_t)b * CD + c) * HP + i) * HP + j];
            }
        }
    }
    float inv = cnt > 0 ? 1.0f / (float)cnt : 0.0f;
#pragma unroll
    for (int k = 0; k < 3; k++) {
        int c = threadIdx.x + k * 256;
        g_means[((size_t)b * NSEG + s) * CD + c] = acc[k] * inv;
    }
}

// -------- fused paint + antialiased bilinear 336->48 (per output pixel) -----
__global__ void paint_resize_k(const int* __restrict__ segmap) {
    const int X = blockIdx.x, Y = blockIdx.y, b = blockIdx.z;
    const int t = threadIdx.x;
    __shared__ float wseg[NSEG];
    __shared__ float wy[15], wx[15];

    if (t < NSEG) wseg[t] = 0.f;
    if (t == 0) {
        float sf = 7.0f * Y + 3.0f, norm = 0.f;
        for (int k = 0; k < 15; k++) {
            int y = 7 * Y - 4 + k;
            float w = (y >= 0 && y < HIMG)
                          ? fmaxf(0.f, 1.f - fabsf((float)y - sf) * (1.f / 7.f))
                          : 0.f;
            wy[k] = w; norm += w;
        }
        float inv = 1.f / norm;
        for (int k = 0; k < 15; k++) wy[k] *= inv;
    }
    if (t == 1) {
        float sf = 7.0f * X + 3.0f, norm = 0.f;
        for (int k = 0; k < 15; k++) {
            int x = 7 * X - 4 + k;
            float w = (x >= 0 && x < HIMG)
                          ? fmaxf(0.f, 1.f - fabsf((float)x - sf) * (1.f / 7.f))
                          : 0.f;
            wx[k] = w; norm += w;
        }
        float inv = 1.f / norm;
        for (int k = 0; k < 15; k++) wx[k] *= inv;
    }
    __syncthreads();

    if (t < 225) {
        int ty = t / 15, tx = t % 15;
        int y = 7 * Y - 4 + ty, x = 7 * X - 4 + tx;
        if (y >= 0 && y < HIMG && x >= 0 && x < HIMG) {
            float w = wy[ty] * wx[tx];
            if (w != 0.f) {
                int seg = segmap[((size_t)b * HIMG + y) * HIMG + x];
                seg = min(max(seg, 0), NSEG - 1);
                atomicAdd(&wseg[seg], w);
            }
        }
    }
    __syncthreads();

    const float* M = g_means + (size_t)b * NSEG * CD;
    const int p = Y * RH + X;
    for (int c = t; c < CD; c += 256) {
        float a = 0.f;
#pragma unroll 16
        for (int s = 0; s < NSEG; s++) a = fmaf(wseg[s], M[(size_t)s * CD + c], a);
        g_sem[((size_t)b * CD + c) * P2 + p] = a;
    }
}

// ---------------- layernorm stats, float4 ----------------------------------
__global__ void ln_stats4_k(const float4* __restrict__ x, int n4PerB, int layer) {
    const int b = blockIdx.y;
    const float4* xb = x + (size_t)b * n4PerB;
    float s = 0.f, s2 = 0.f;
    for (int i = blockIdx.x * blockDim.x + threadIdx.x; i < n4PerB;
         i += gridDim.x * blockDim.x) {
        float4 v = xb[i];
        s += (v.x + v.y) + (v.z + v.w);
        s2 = fmaf(v.x, v.x, fmaf(v.y, v.y, fmaf(v.z, v.z, fmaf(v.w, v.w, s2))));
    }
#pragma unroll
    for (int o = 16; o; o >>= 1) {
        s += __shfl_down_sync(0xffffffffu, s, o);
        s2 += __shfl_down_sync(0xffffffffu, s2, o);
    }
    __shared__ float sh[32][2];
    int w = threadIdx.x >> 5, l = threadIdx.x & 31;
    if (l == 0) { sh[w][0] = s; sh[w][1] = s2; }
    __syncthreads();
    if (threadIdx.x < 32) {
        int nw = blockDim.x >> 5;
        s = (threadIdx.x < nw) ? sh[threadIdx.x][0] : 0.f;
        s2 = (threadIdx.x < nw) ? sh[threadIdx.x][1] : 0.f;
#pragma unroll
        for (int o = 16; o; o >>= 1) {
            s += __shfl_down_sync(0xffffffffu, s, o);
            s2 += __shfl_down_sync(0xffffffffu, s2, o);
        }
        if (threadIdx.x == 0) {
            atomicAdd(&g_stats[layer * 4 + b * 2 + 0], s);
            atomicAdd(&g_stats[layer * 4 + b * 2 + 1], s2);
        }
    }
}

// ------- stage CI channels of an 18x18 halo patch, row stride 20 ------------
__device__ __forceinline__ void stage_patch(float* sp, const float* __restrict__ in,
                                            int ci0, int ty0, int tx0, int t) {
    for (int idx = t; idx < CI * 324; idx += 256) {
        int ci = idx / 324, q = idx - ci * 324;
        int row = q / 18, col = q - row * 18;
        int y = ty0 + row - 1, x = tx0 + col - 1;
        float v = 0.f;
        if ((unsigned)y < RH && (unsigned)x < RH)
            v = in[(size_t)(ci0 + ci) * P2 + y * RH + x];
        sp[ci * 360 + row * 20 + col] = v;
    }
}

__device__ __forceinline__ void load_rv(float rv[3][6], const float* pb) {
#pragma unroll
    for (int ky = 0; ky < 3; ky++) {
        float4 a = *(const float4*)(pb + ky * 20);
        float2 c2 = *(const float2*)(pb + ky * 20 + 4);
        rv[ky][0] = a.x; rv[ky][1] = a.y; rv[ky][2] = a.z; rv[ky][3] = a.w;
        rv[ky][4] = c2.x; rv[ky][5] = c2.y;
    }
}

// ------- shared 3x3 conv 768->128 + bias + relu, all 3 layers (z=0..5) ------
__global__ void __launch_bounds__(256) shconv_k(
    const float* __restrict__ ws0, const float* __restrict__ ws1,
    const float* __restrict__ ws2, const float* __restrict__ bs0,
    const float* __restrict__ bs1, const float* __restrict__ bs2) {
    __shared__ float sp[CI * 360];
    __shared__ float wsm[16 * WSTR];
    const int tile = blockIdx.x;
    const int ty0 = (tile / 3) * 16, tx0 = (tile % 3) * 16;
    const int co0 = blockIdx.y * 16;
    const int z = blockIdx.z, layer = z >> 1, b = z & 1;
    const float* wt = layer == 0 ? ws0 : (layer == 1 ? ws1 : ws2);
    const float* bias = layer == 0 ? bs0 : (layer == 1 ? bs1 : bs2);
    const float* in = g_sem + (size_t)b * CD * P2;
    float* outp = g_h + (size_t)z * HID * P2;
    const int t = threadIdx.x;
    const int co_i = t & 3, g = t >> 2, r = g >> 2, q = g & 3;

    float acc[4][4];
#pragma unroll
    for (int j = 0; j < 4; j++)
#pragma unroll
        for (int p = 0; p < 4; p++) acc[j][p] = 0.f;

    for (int cb = 0; cb < CD; cb += CI) {
        __syncthreads();
        stage_patch(sp, in, cb, ty0, tx0, t);
        for (int idx = t; idx < 16 * CI * 9; idx += 256) {
            int co_l = idx / 72, rem = idx - co_l * 72;
            int ci = rem / 9, tap = rem - ci * 9;
            wsm[co_l * WSTR + ci * 12 + tap] =
                wt[((size_t)(co0 + co_l) * CD + cb + ci) * 9 + tap];
        }
        __syncthreads();
#pragma unroll
        for (int ci = 0; ci < CI; ci++) {
            float rv[3][6];
            load_rv(rv, sp + ci * 360 + r * 20 + q * 4);
#pragma unroll
            for (int j = 0; j < 4; j++) {
                const float* wp = wsm + (co_i * 4 + j) * WSTR + ci * 12;
                float4 w0 = *(const float4*)wp;
                float4 w1 = *(const float4*)(wp + 4);
                float w8 = wp[8];
                float w[9] = {w0.x, w0.y, w0.z, w0.w, w1.x, w1.y, w1.z, w1.w, w8};
#pragma unroll
                for (int ky = 0; ky < 3; ky++)
#pragma unroll
                    for (int kx = 0; kx < 3; kx++)
#pragma unroll
                        for (int p = 0; p < 4; p++)
                            acc[j][p] = fmaf(rv[ky][kx + p], w[ky * 3 + kx], acc[j][p]);
            }
        }
    }
    const int pg = (ty0 + r) * RH + tx0 + q * 4;
#pragma unroll
    for (int j = 0; j < 4; j++) {
        int c = co0 + co_i * 4 + j;
        float bv = bias[c];
        float4 o;
        o.x = fmaxf(acc[j][0] + bv, 0.f);
        o.y = fmaxf(acc[j][1] + bv, 0.f);
        o.z = fmaxf(acc[j][2] + bv, 0.f);
        o.w = fmaxf(acc[j][3] + bv, 0.f);
        *(float4*)(outp + (size_t)c * P2 + pg) = o;
    }
}

// ------- layer0: gamma/beta conv (128->3072) + LN apply -> act0 -------------
__global__ void __launch_bounds__(256) spade0_k(
    const float* __restrict__ wg, const float* __restrict__ bg,
    const float* __restrict__ wb, const float* __restrict__ bb,
    const float* __restrict__ x) {
    __shared__ float sp[CI * 360];
    __shared__ float wga[16 * WSTR];
    __shared__ float wba[16 * WSTR];
    const int tile = blockIdx.x;
    const int ty0 = (tile / 3) * 16, tx0 = (tile % 3) * 16;
    const int co0 = blockIdx.y * 16;
    const int b = blockIdx.z;
    const float* hin = g_h + (size_t)b * HID * P2;  // layer0 slabs = z 0,1
    const int t = threadIdx.x;
    const int co_i = t & 3, g = t >> 2, r = g >> 2, q = g & 3;

    float accg[4][4], accb[4][4];
#pragma unroll
    for (int j = 0; j < 4; j++)
#pragma unroll
        for (int p = 0; p < 4; p++) { accg[j][p] = 0.f; accb[j][p] = 0.f; }

    for (int cb = 0; cb < HID; cb += CI) {
        __syncthreads();
        stage_patch(sp, hin, cb, ty0, tx0, t);
        for (int idx = t; idx < 16 * CI * 9; idx += 256) {
            int co_l = idx / 72, rem = idx - co_l * 72;
            int ci = rem / 9, tap = rem - ci * 9;
            size_t wi = ((size_t)(co0 + co_l) * HID + cb + ci) * 9 + tap;
            int si = co_l * WSTR + ci * 12 + tap;
            wga[si] = wg[wi];
            wba[si] = wb[wi];
        }
        __syncthreads();
#pragma unroll
        for (int ci = 0; ci < CI; ci++) {
            float rv[3][6];
            load_rv(rv, sp + ci * 360 + r * 20 + q * 4);
#pragma unroll
            for (int j = 0; j < 4; j++) {
                const float* wpg = wga + (co_i * 4 + j) * WSTR + ci * 12;
                const float* wpb = wba + (co_i * 4 + j) * WSTR + ci * 12;
                float4 a0 = *(const float4*)wpg;
                float4 a1 = *(const float4*)(wpg + 4);
                float a8 = wpg[8];
                float wa[9] = {a0.x, a0.y, a0.z, a0.w, a1.x, a1.y, a1.z, a1.w, a8};
                float4 c0 = *(const float4*)wpb;
                float4 c1 = *(const float4*)(wpb + 4);
                float c8 = wpb[8];
                float wc[9] = {c0.x, c0.y, c0.z, c0.w, c1.x, c1.y, c1.z, c1.w, c8};
#pragma unroll
                for (int ky = 0; ky < 3; ky++)
#pragma unroll
                    for (int kx = 0; kx < 3; kx++)
#pragma unroll
                        for (int p = 0; p < 4; p++) {
                            accg[j][p] = fmaf(rv[ky][kx + p], wa[ky * 3 + kx], accg[j][p]);
                            accb[j][p] = fmaf(rv[ky][kx + p], wc[ky * 3 + kx], accb[j][p]);
                        }
            }
        }
    }
    const float sum = g_stats[b * 2 + 0], sumsq = g_stats[b * 2 + 1];
    const float invN = 1.f / ((float)CM * P2);
    const float mean = sum * invN;
    const float rstd = rsqrtf(sumsq * invN - mean * mean + LNEPS);

    const int pg = (ty0 + r) * RH + tx0 + q * 4;
#pragma unroll
    for (int j = 0; j < 4; j++) {
        int c = co0 + co_i * 4 + j;
        float bgv = bg[c], bbv = bb[c];
        size_t base = ((size_t)b * CM + c) * P2 + pg;
        float4 xv = *(const float4*)(x + base);
        float4 o;
        o.x = fmaf((xv.x - mean) * rstd, 1.f + accg[j][0] + bgv, accb[j][0] + bbv);
        o.y = fmaf((xv.y - mean) * rstd, 1.f + accg[j][1] + bgv, accb[j][1] + bbv);
        o.z = fmaf((xv.z - mean) * rstd, 1.f + accg[j][2] + bgv, accb[j][2] + bbv);
        o.w = fmaf((xv.w - mean) * rstd, 1.f + accg[j][3] + bgv, accb[j][3] + bbv);
        *(float4*)(g_act0 + base) = o;
    }
}

// ------- small spade (layers 1/2): 8 couts/block, as before -----------------
__global__ void spade_apply_k(const float* __restrict__ hin,
                              const float* __restrict__ wg, const float* __restrict__ bg,
                              const float* __restrict__ wb, const float* __restrict__ bb,
                              const float* __restrict__ x, float* __restrict__ act,
                              int layer, float invN) {
    const int tile = blockIdx.x;
    const int ty0 = (tile / 3) * 16, tx0 = (tile % 3) * 16;
    const int co0 = blockIdx.y * 8;
    const int nf = gridDim.y * 8;
    const int b = blockIdx.z;
    const int t = threadIdx.x;
    const int py = t >> 4, px = t & 15;

    __shared__ float sin_s[8][324];
    __shared__ float swg[8][8][9];
    __shared__ float swb[8][8][9];

    float accg[8], accb[8];
#pragma unroll
    for (int i = 0; i < 8; i++) { accg[i] = 0.f; accb[i] = 0.f; }

    const size_t inB = (size_t)b * HID * P2;
    for (int cb = 0; cb < HID; cb += 8) {
        for (int idx = t; idx < 8 * 324; idx += 256) {
            int c = idx / 324, q = idx - c * 324;
            int iy = ty0 + q / 18 - 1, ix = tx0 + (q % 18) - 1;
            float v = 0.f;
            if ((unsigned)iy < RH && (unsigned)ix < RH)
                v = hin[inB + (size_t)(cb + c) * P2 + iy * RH + ix];
            sin_s[c][q] = v;
        }
        for (int idx = t; idx < 576; idx += 256) {
            int co = idx / 72, rr = idx - co * 72;
            size_t wi = ((size_t)(co0 + co) * HID + cb + rr / 9) * 9 + (rr % 9);
            swg[co][rr / 9][rr % 9] = wg[wi];
            swb[co][rr / 9][rr % 9] = wb[wi];
        }
        __syncthreads();
#pragma unroll
        for (int ci = 0; ci < 8; ci++) {
            float v[9];
#pragma unroll
            for (int ky = 0; ky < 3; ky++)
#pragma unroll
                for (int kx = 0; kx < 3; kx++)
                    v[ky * 3 + kx] = sin_s[ci][(py + ky) * 18 + px + kx];
#pragma unroll
            for (int co = 0; co < 8; co++) {
                float ag = accg[co], ab = accb[co];
#pragma unroll
                for (int k = 0; k < 9; k++) {
                    ag = fmaf(v[k], swg[co][ci][k], ag);
                    ab = fmaf(v[k], swb[co][ci][k], ab);
                }
                accg[co] = ag; accb[co] = ab;
            }
        }
        __syncthreads();
    }

    const float sum = g_stats[layer * 4 + b * 2 + 0];
    const float sumsq = g_stats[layer * 4 + b * 2 + 1];
    const float mean = sum * invN;
    const float rstd = rsqrtf(sumsq * invN - mean * mean + LNEPS);

    const int p = (ty0 + py) * RH + tx0 + px;
#pragma unroll
    for (int co = 0; co < 8; co++) {
        int c = co0 + co;
        float gv = accg[co] + bg[c];
        float be = accb[co] + bb[c];
        float xv = x[((size_t)b * nf + c) * P2 + p];
        act[((size_t)b * nf + c) * P2 + p] = fmaf((xv - mean) * rstd, 1.f + gv, be);
    }
}

// ---------------- 1x1 conv + softplus --------------------------------------
__device__ __forceinline__ float softplus_f(float z) {
    return fmaxf(z, 0.f) + log1pf(expf(-fabsf(z)));
}

template <int COUT>
__global__ void conv1x1_softplus_k(const float* __restrict__ act,
                                   const float* __restrict__ w,
                                   const float* __restrict__ bias,
                                   float* __restrict__ out, int Cin) {
    const int p = blockIdx.x * blockDim.x + threadIdx.x;
    const int b = blockIdx.y;
    float acc[COUT];
#pragma unroll
    for (int j = 0; j < COUT; j++) acc[j] = 0.f;
    const float* ab = act + (size_t)b * Cin * P2 + p;
#pragma unroll 4
    for (int c = 0; c < Cin; c++) {
        float v = ab[(size_t)c * P2];
#pragma unroll
        for (int j = 0; j < COUT; j++)
            acc[j] = fmaf(__ldg(&w[(size_t)j * Cin + c]), v, acc[j]);
    }
#pragma unroll
    for (int j = 0; j < COUT; j++)
        out[((size_t)b * COUT + j) * P2 + p] = softplus_f(acc[j] + bias[j]);
}

// ---------------------------------------------------------------------------
static float* sym_ptr(const void* sym) {
    void* p = nullptr;
    cudaGetSymbolAddress(&p, sym);
    return (float*)p;
}

extern "C" void kernel_launch(void* const* d_in, const int* in_sizes, int n_in,
                              void* d_out, int out_size) {
    const float* x_main = (const float*)d_in[0];
    const float* f_sem = (const float*)d_in[1];
    const int* segmap = (const int*)d_in[2];
    const float* ws[3] = {(const float*)d_in[3], (const float*)d_in[9], (const float*)d_in[15]};
    const float* bs[3] = {(const float*)d_in[4], (const float*)d_in[10], (const float*)d_in[16]};
    const float* wg[3] = {(const float*)d_in[5], (const float*)d_in[11], (const float*)d_in[17]};
    const float* bg[3] = {(const float*)d_in[6], (const float*)d_in[12], (const float*)d_in[18]};
    const float* wb[3] = {(const float*)d_in[7], (const float*)d_in[13], (const float*)d_in[19]};
    const float* bb[3] = {(const float*)d_in[8], (const float*)d_in[14], (const float*)d_in[20]};
    const float* w1x[3] = {(const float*)d_in[21], (const float*)d_in[23], (const float*)d_in[25]};
    const float* b1x[3] = {(const float*)d_in[22], (const float*)d_in[24], (const float*)d_in[26]};
    float* out = (float*)d_out;

    float* p_h = sym_ptr(g_h);
    float* p_act0 = sym_ptr(g_act0);
    float* p_x1 = sym_ptr(g_x1);
    float* p_act1 = sym_ptr(g_act1);
    float* p_x2 = sym_ptr(g_x2);
    float* p_act2 = sym_ptr(g_act2);

    zero_stats_k<<<1, 32>>>();
    seg_means_k<<<dim3(NSEG, NB), 256>>>(f_sem, segmap);
    paint_resize_k<<<dim3(RH, RH, NB), 256>>>(segmap);

    // shared 768->128 convs for all three layers
    shconv_k<<<dim3(9, HID / 16, 6), 256>>>(ws[0], ws[1], ws[2], bs[0], bs[1], bs[2]);

    // ---- layer 0 ----
    ln_stats4_k<<<dim3(256, NB), 256>>>((const float4*)x_main, CM * P2 / 4, 0);
    spade0_k<<<dim3(9, CM / 16, NB), 256>>>(wg[0], bg[0], wb[0], bb[0], x_main);
    conv1x1_softplus_k<8><<<dim3(9, NB), 256>>>(p_act0, w1x[0], b1x[0], p_x1, CM);

    // ---- layer 1 ----
    ln_stats4_k<<<dim3(2, NB), 256>>>((const float4*)p_x1, 8 * P2 / 4, 1);
    spade_apply_k<<<dim3(9, 1, NB), 256>>>(p_h + (size_t)1 * NB * HID * P2,
                                           wg[1], bg[1], wb[1], bb[1],
                                           p_x1, p_act1, 1, 1.f / (8 * P2));
    conv1x1_softplus_k<16><<<dim3(9, NB), 256>>>(p_act1, w1x[1], b1x[1], p_x2, 8);

    // ---- layer 2 ----
    ln_stats4_k<<<dim3(2, NB), 256>>>((const float4*)p_x2, 16 * P2 / 4, 2);
    spade_apply_k<<<dim3(9, 2, NB), 256>>>(p_h + (size_t)2 * NB * HID * P2,
                                           wg[2], bg[2], wb[2], bb[2],
                                           p_x2, p_act2, 2, 1.f / (16 * P2));
    conv1x1_softplus_k<1><<<dim3(9, NB), 256>>>(p_act2, w1x[2], b1x[2], out, 16);
}

// round 4
// speedup vs baseline: 1.9933x; 1.5202x over previous
#include <cuda_runtime.h>
#include <math.h>

#define NB 2
#define NSEG 64
#define HIMG 336
#define HP 24
#define CD 768
#define CM 3072
#define RH 48
#define HID 128
#define P2 2304
#define LNEPS 1e-12f

typedef unsigned long long ull;
#define FFMA2(acc, a, b) asm("fma.rn.f32x2 %0, %1, %2, %0;" : "+l"(acc) : "l"(a), "l"(b))
#define UNPK(lo, hi, s) asm("mov.b64 {%0,%1}, %2;" : "=f"(lo), "=f"(hi) : "l"(s))

__device__ float g_means[NB * NSEG * CD];
__device__ float g_sem[(size_t)NB * CD * P2];
__device__ float g_h[(size_t)3 * NB * HID * P2];
__device__ float g_act0[(size_t)NB * CM * P2];
__device__ float g_red[NB * 12 * 8 * P2];
__device__ float g_x1[NB * 8 * P2];
__device__ float g_act1[NB * 8 * P2];
__device__ float g_x2[NB * 16 * P2];
__device__ float g_act2[NB * 16 * P2];
__device__ float g_stats[12];

__global__ void zero_stats_k() {
    if (threadIdx.x < 12) g_stats[threadIdx.x] = 0.f;
}

// ---------------- per-segment channel means (24x24 nearest segmap) ----------
__global__ void seg_means_k(const float* __restrict__ f_sem,
                            const int* __restrict__ segmap) {
    const int s = blockIdx.x, b = blockIdx.y;
    __shared__ int segs[HP * HP];
    for (int p = threadIdx.x; p < HP * HP; p += 256) {
        int i = p / HP, j = p % HP;
        int v = segmap[((size_t)b * HIMG + i * 14) * HIMG + j * 14];
        segs[p] = min(max(v, 0), NSEG - 1);
    }
    __syncthreads();
    float acc[3] = {0.f, 0.f, 0.f};
    int cnt = 0;
    for (int p = 0; p < HP * HP; p++) {
        if (segs[p] == s) {
            cnt++;
            int i = p / HP, j = p % HP;
#pragma unroll
            for (int k = 0; k < 3; k++) {
                int c = threadIdx.x + k * 256;
                acc[k] += f_sem[(((size_t)b * CD + c) * HP + i) * HP + j];
            }
        }
    }
    float inv = cnt > 0 ? 1.0f / (float)cnt : 0.0f;
#pragma unroll
    for (int k = 0; k < 3; k++) {
        int c = threadIdx.x + k * 256;
        g_means[((size_t)b * NSEG + s) * CD + c] = acc[k] * inv;
    }
}

// -------- fused paint + antialiased bilinear 336->48 ------------------------
__global__ void paint_resize_k(const int* __restrict__ segmap) {
    const int X = blockIdx.x, Y = blockIdx.y, b = blockIdx.z;
    const int t = threadIdx.x;
    __shared__ float wseg[NSEG];
    __shared__ float wy[15], wx[15];

    if (t < NSEG) wseg[t] = 0.f;
    if (t == 0) {
        float sf = 7.0f * Y + 3.0f, norm = 0.f;
        for (int k = 0; k < 15; k++) {
            int y = 7 * Y - 4 + k;
            float w = (y >= 0 && y < HIMG)
                          ? fmaxf(0.f, 1.f - fabsf((float)y - sf) * (1.f / 7.f)) : 0.f;
            wy[k] = w; norm += w;
        }
        float inv = 1.f / norm;
        for (int k = 0; k < 15; k++) wy[k] *= inv;
    }
    if (t == 1) {
        float sf = 7.0f * X + 3.0f, norm = 0.f;
        for (int k = 0; k < 15; k++) {
            int x = 7 * X - 4 + k;
            float w = (x >= 0 && x < HIMG)
                          ? fmaxf(0.f, 1.f - fabsf((float)x - sf) * (1.f / 7.f)) : 0.f;
            wx[k] = w; norm += w;
        }
        float inv = 1.f / norm;
        for (int k = 0; k < 15; k++) wx[k] *= inv;
    }
    __syncthreads();

    if (t < 225) {
        int ty = t / 15, tx = t % 15;
        int y = 7 * Y - 4 + ty, x = 7 * X - 4 + tx;
        if (y >= 0 && y < HIMG && x >= 0 && x < HIMG) {
            float w = wy[ty] * wx[tx];
            if (w != 0.f) {
                int seg = segmap[((size_t)b * HIMG + y) * HIMG + x];
                seg = min(max(seg, 0), NSEG - 1);
                atomicAdd(&wseg[seg], w);
            }
        }
    }
    __syncthreads();

    const float* M = g_means + (size_t)b * NSEG * CD;
    const int p = Y * RH + X;
    for (int c = t; c < CD; c += 256) {
        float a = 0.f;
#pragma unroll 16
        for (int s = 0; s < NSEG; s++) a = fmaf(wseg[s], M[(size_t)s * CD + c], a);
        g_sem[((size_t)b * CD + c) * P2 + p] = a;
    }
}

// ---------------- layernorm stats, float4 ----------------------------------
__global__ void ln_stats4_k(const float4* __restrict__ x, int n4PerB, int layer) {
    const int b = blockIdx.y;
    const float4* xb = x + (size_t)b * n4PerB;
    float s = 0.f, s2 = 0.f;
    for (int i = blockIdx.x * blockDim.x + threadIdx.x; i < n4PerB;
         i += gridDim.x * blockDim.x) {
        float4 v = xb[i];
        s += (v.x + v.y) + (v.z + v.w);
        s2 = fmaf(v.x, v.x, fmaf(v.y, v.y, fmaf(v.z, v.z, fmaf(v.w, v.w, s2))));
    }
#pragma unroll
    for (int o = 16; o; o >>= 1) {
        s += __shfl_down_sync(0xffffffffu, s, o);
        s2 += __shfl_down_sync(0xffffffffu, s2, o);
    }
    __shared__ float sh[32][2];
    int w = threadIdx.x >> 5, l = threadIdx.x & 31;
    if (l == 0) { sh[w][0] = s; sh[w][1] = s2; }
    __syncthreads();
    if (threadIdx.x < 32) {
        int nw = blockDim.x >> 5;
        s = (threadIdx.x < nw) ? sh[threadIdx.x][0] : 0.f;
        s2 = (threadIdx.x < nw) ? sh[threadIdx.x][1] : 0.f;
#pragma unroll
        for (int o = 16; o; o >>= 1) {
            s += __shfl_down_sync(0xffffffffu, s, o);
            s2 += __shfl_down_sync(0xffffffffu, s2, o);
        }
        if (threadIdx.x == 0) {
            atomicAdd(&g_stats[layer * 4 + b * 2 + 0], s);
            atomicAdd(&g_stats[layer * 4 + b * 2 + 1], s2);
        }
    }
}

// ---- stage CI channels of 18x18 patch into 3 kx-shifted copies (stride 20) --
template <int CI, int NT>
__device__ __forceinline__ void stage3(float* scp, const float* __restrict__ in,
                                       int cb, int ty0, int tx0, int t) {
    for (int idx = t; idx < CI * 324; idx += NT) {
        int ci = idx / 324, q = idx - ci * 324;
        int row = q / 18, c = q - row * 18;
        int y = ty0 + row - 1, x = tx0 + c - 1;
        float v = 0.f;
        if ((unsigned)y < RH && (unsigned)x < RH)
            v = in[(size_t)(cb + ci) * P2 + y * RH + x];
#pragma unroll
        for (int kx = 0; kx < 3; kx++) {
            int cc = c - kx;
            if ((unsigned)cc < 16u)
                scp[((kx * CI + ci) * 18 + row) * 20 + cc] = v;
        }
    }
}

// ------- shared 3x3 conv 768->128 + bias + relu, all 3 layers (z=0..5) ------
// 128 threads: co_i=t&3 (4 couts each), g=t>>2: r=g>>1 (row), hh=g&1 (8-px half)
#define SCI 8
__global__ void __launch_bounds__(128) shconv_k(
    const float* __restrict__ ws0, const float* __restrict__ ws1,
    const float* __restrict__ ws2, const float* __restrict__ bs0,
    const float* __restrict__ bs1, const float* __restrict__ bs2) {
    __shared__ __align__(16) float scp[3 * SCI * 18 * 20];
    __shared__ __align__(16) float2 wdup[SCI * 9 * 16];
    const int tile = blockIdx.x;
    const int ty0 = (tile / 3) * 16, tx0 = (tile % 3) * 16;
    const int co0 = blockIdx.y * 16;
    const int z = blockIdx.z, layer = z >> 1, b = z & 1;
    const float* wt = layer == 0 ? ws0 : (layer == 1 ? ws1 : ws2);
    const float* bias = layer == 0 ? bs0 : (layer == 1 ? bs1 : bs2);
    const float* in = g_sem + (size_t)b * CD * P2;
    float* outp = g_h + (size_t)z * HID * P2;
    const int t = threadIdx.x;
    const int co_i = t & 3, g = t >> 2, r = g >> 1, hh = g & 1;

    ull acc[4][4];
#pragma unroll
    for (int j = 0; j < 4; j++)
#pragma unroll
        for (int i = 0; i < 4; i++) acc[j][i] = 0ULL;

    for (int cb = 0; cb < CD; cb += SCI) {
        __syncthreads();
        stage3<SCI, 128>(scp, in, cb, ty0, tx0, t);
        for (int idx = t; idx < 16 * SCI * 9; idx += 128) {
            int co_l = idx / (SCI * 9), rem = idx - co_l * (SCI * 9);
            int ci = rem / 9, tap = rem - ci * 9;
            float w = wt[((size_t)(co0 + co_l) * CD + cb + ci) * 9 + tap];
            wdup[(ci * 9 + tap) * 16 + co_l] = make_float2(w, w);
        }
        __syncthreads();
#pragma unroll
        for (int ci = 0; ci < SCI; ci++) {
#pragma unroll
            for (int ky = 0; ky < 3; ky++) {
#pragma unroll
                for (int kx = 0; kx < 3; kx++) {
                    const ulonglong2* pp = (const ulonglong2*)(scp +
                        ((kx * SCI + ci) * 18 + r + ky) * 20 + hh * 8);
                    ulonglong2 pA = pp[0], pB = pp[1];
                    const ulonglong2* wp = (const ulonglong2*)(wdup +
                        (ci * 9 + ky * 3 + kx) * 16 + co_i * 4);
                    ulonglong2 w01 = wp[0], w23 = wp[1];
                    FFMA2(acc[0][0], pA.x, w01.x); FFMA2(acc[0][1], pA.y, w01.x);
                    FFMA2(acc[0][2], pB.x, w01.x); FFMA2(acc[0][3], pB.y, w01.x);
                    FFMA2(acc[1][0], pA.x, w01.y); FFMA2(acc[1][1], pA.y, w01.y);
                    FFMA2(acc[1][2], pB.x, w01.y); FFMA2(acc[1][3], pB.y, w01.y);
                    FFMA2(acc[2][0], pA.x, w23.x); FFMA2(acc[2][1], pA.y, w23.x);
                    FFMA2(acc[2][2], pB.x, w23.x); FFMA2(acc[2][3], pB.y, w23.x);
                    FFMA2(acc[3][0], pA.x, w23.y); FFMA2(acc[3][1], pA.y, w23.y);
                    FFMA2(acc[3][2], pB.x, w23.y); FFMA2(acc[3][3], pB.y, w23.y);
                }
            }
        }
    }
    const int pg = (ty0 + r) * RH + tx0 + hh * 8;
#pragma unroll
    for (int j = 0; j < 4; j++) {
        int c = co0 + co_i * 4 + j;
        float bv = bias[c];
        float f[8];
#pragma unroll
        for (int i = 0; i < 4; i++) UNPK(f[2 * i], f[2 * i + 1], acc[j][i]);
        float4 o0, o1;
        o0.x = fmaxf(f[0] + bv, 0.f); o0.y = fmaxf(f[1] + bv, 0.f);
        o0.z = fmaxf(f[2] + bv, 0.f); o0.w = fmaxf(f[3] + bv, 0.f);
        o1.x = fmaxf(f[4] + bv, 0.f); o1.y = fmaxf(f[5] + bv, 0.f);
        o1.z = fmaxf(f[6] + bv, 0.f); o1.w = fmaxf(f[7] + bv, 0.f);
        *(float4*)(outp + (size_t)c * P2 + pg) = o0;
        *(float4*)(outp + (size_t)c * P2 + pg + 4) = o1;
    }
}

// ------- layer0: dual gamma/beta conv (128->3072) + LN apply -> act0 --------
#define PCI 4
__global__ void __launch_bounds__(128) spade0_k(
    const float* __restrict__ wg, const float* __restrict__ bg,
    const float* __restrict__ wb, const float* __restrict__ bb,
    const float* __restrict__ x) {
    __shared__ __align__(16) float scp[3 * PCI * 18 * 20];
    __shared__ __align__(16) float2 wgd[PCI * 9 * 16];
    __shared__ __align__(16) float2 wbd[PCI * 9 * 16];
    const int tile = blockIdx.x;
    const int ty0 = (tile / 3) * 16, tx0 = (tile % 3) * 16;
    const int co0 = blockIdx.y * 16;
    const int b = blockIdx.z;
    const float* hin = g_h + (size_t)b * HID * P2;
    const int t = threadIdx.x;
    const int co_i = t & 3, g = t >> 2, r = g >> 1, hh = g & 1;

    ull ag[4][4], ab[4][4];
#pragma unroll
    for (int j = 0; j < 4; j++)
#pragma unroll
        for (int i = 0; i < 4; i++) { ag[j][i] = 0ULL; ab[j][i] = 0ULL; }

    for (int cb = 0; cb < HID; cb += PCI) {
        __syncthreads();
        stage3<PCI, 128>(scp, hin, cb, ty0, tx0, t);
        for (int idx = t; idx < 16 * PCI * 9; idx += 128) {
            int co_l = idx / (PCI * 9), rem = idx - co_l * (PCI * 9);
            int ci = rem / 9, tap = rem - ci * 9;
            size_t wi = ((size_t)(co0 + co_l) * HID + cb + ci) * 9 + tap;
            float a = wg[wi], c = wb[wi];
            wgd[(ci * 9 + tap) * 16 + co_l] = make_float2(a, a);
            wbd[(ci * 9 + tap) * 16 + co_l] = make_float2(c, c);
        }
        __syncthreads();
#pragma unroll
        for (int ci = 0; ci < PCI; ci++) {
#pragma unroll
            for (int ky = 0; ky < 3; ky++) {
#pragma unroll
                for (int kx = 0; kx < 3; kx++) {
                    const ulonglong2* pp = (const ulonglong2*)(scp +
                        ((kx * PCI + ci) * 18 + r + ky) * 20 + hh * 8);
                    ulonglong2 pA = pp[0], pB = pp[1];
                    int tap16 = (ci * 9 + ky * 3 + kx) * 16 + co_i * 4;
                    const ulonglong2* wpg = (const ulonglong2*)(wgd + tap16);
                    const ulonglong2* wpb = (const ulonglong2*)(wbd + tap16);
                    ulonglong2 g01 = wpg[0], g23 = wpg[1];
                    ulonglong2 b01 = wpb[0], b23 = wpb[1];
                    FFMA2(ag[0][0], pA.x, g01.x); FFMA2(ag[0][1], pA.y, g01.x);
                    FFMA2(ag[0][2], pB.x, g01.x); FFMA2(ag[0][3], pB.y, g01.x);
                    FFMA2(ag[1][0], pA.x, g01.y); FFMA2(ag[1][1], pA.y, g01.y);
                    FFMA2(ag[1][2], pB.x, g01.y); FFMA2(ag[1][3], pB.y, g01.y);
                    FFMA2(ag[2][0], pA.x, g23.x); FFMA2(ag[2][1], pA.y, g23.x);
                    FFMA2(ag[2][2], pB.x, g23.x); FFMA2(ag[2][3], pB.y, g23.x);
                    FFMA2(ag[3][0], pA.x, g23.y); FFMA2(ag[3][1], pA.y, g23.y);
                    FFMA2(ag[3][2], pB.x, g23.y); FFMA2(ag[3][3], pB.y, g23.y);
                    FFMA2(ab[0][0], pA.x, b01.x); FFMA2(ab[0][1], pA.y, b01.x);
                    FFMA2(ab[0][2], pB.x, b01.x); FFMA2(ab[0][3], pB.y, b01.x);
                    FFMA2(ab[1][0], pA.x, b01.y); FFMA2(ab[1][1], pA.y, b01.y);
                    FFMA2(ab[1][2], pB.x, b01.y); FFMA2(ab[1][3], pB.y, b01.y);
                    FFMA2(ab[2][0], pA.x, b23.x); FFMA2(ab[2][1], pA.y, b23.x);
                    FFMA2(ab[2][2], pB.x, b23.x); FFMA2(ab[2][3], pB.y, b23.x);
                    FFMA2(ab[3][0], pA.x, b23.y); FFMA2(ab[3][1], pA.y, b23.y);
                    FFMA2(ab[3][2], pB.x, b23.y); FFMA2(ab[3][3], pB.y, b23.y);
                }
            }
        }
    }
    const float sum = g_stats[b * 2 + 0], sumsq = g_stats[b * 2 + 1];
    const float invN = 1.f / ((float)CM * P2);
    const float mean = sum * invN;
    const float rstd = rsqrtf(sumsq * invN - mean * mean + LNEPS);

    const int pg = (ty0 + r) * RH + tx0 + hh * 8;
#pragma unroll
    for (int j = 0; j < 4; j++) {
        int c = co0 + co_i * 4 + j;
        float bgv = bg[c], bbv = bb[c];
        float fg[8], fb[8];
#pragma unroll
        for (int i = 0; i < 4; i++) {
            UNPK(fg[2 * i], fg[2 * i + 1], ag[j][i]);
            UNPK(fb[2 * i], fb[2 * i + 1], ab[j][i]);
        }
        size_t base = ((size_t)b * CM + c) * P2 + pg;
#pragma unroll
        for (int h = 0; h < 2; h++) {
            float4 xv = *(const float4*)(x + base + h * 4);
            float4 o;
            o.x = fmaf((xv.x - mean) * rstd, 1.f + fg[h * 4 + 0] + bgv, fb[h * 4 + 0] + bbv);
            o.y = fmaf((xv.y - mean) * rstd, 1.f + fg[h * 4 + 1] + bgv, fb[h * 4 + 1] + bbv);
            o.z = fmaf((xv.z - mean) * rstd, 1.f + fg[h * 4 + 2] + bgv, fb[h * 4 + 2] + bbv);
            o.w = fmaf((xv.w - mean) * rstd, 1.f + fg[h * 4 + 3] + bgv, fb[h * 4 + 3] + bbv);
            *(float4*)(g_act0 + base + h * 4) = o;
        }
    }
}

// ------- small spade (layers 1/2) -------------------------------------------
__global__ void spade_apply_k(const float* __restrict__ hin,
                              const float* __restrict__ wg, const float* __restrict__ bg,
                              const float* __restrict__ wb, const float* __restrict__ bb,
                              const float* __restrict__ x, float* __restrict__ act,
                              int layer, float invN) {
    const int tile = blockIdx.x;
    const int ty0 = (tile / 3) * 16, tx0 = (tile % 3) * 16;
    const int co0 = blockIdx.y * 8;
    const int nf = gridDim.y * 8;
    const int b = blockIdx.z;
    const int t = threadIdx.x;
    const int py = t >> 4, px = t & 15;

    __shared__ float sin_s[8][324];
    __shared__ float swg[8][8][9];
    __shared__ float swb[8][8][9];

    float accg[8], accb[8];
#pragma unroll
    for (int i = 0; i < 8; i++) { accg[i] = 0.f; accb[i] = 0.f; }

    const size_t inB = (size_t)b * HID * P2;
    for (int cb = 0; cb < HID; cb += 8) {
        for (int idx = t; idx < 8 * 324; idx += 256) {
            int c = idx / 324, q = idx - c * 324;
            int iy = ty0 + q / 18 - 1, ix = tx0 + (q % 18) - 1;
            float v = 0.f;
            if ((unsigned)iy < RH && (unsigned)ix < RH)
                v = hin[inB + (size_t)(cb + c) * P2 + iy * RH + ix];
            sin_s[c][q] = v;
        }
        for (int idx = t; idx < 576; idx += 256) {
            int co = idx / 72, rr = idx - co * 72;
            size_t wi = ((size_t)(co0 + co) * HID + cb + rr / 9) * 9 + (rr % 9);
            swg[co][rr / 9][rr % 9] = wg[wi];
            swb[co][rr / 9][rr % 9] = wb[wi];
        }
        __syncthreads();
#pragma unroll
        for (int ci = 0; ci < 8; ci++) {
            float v[9];
#pragma unroll
            for (int ky = 0; ky < 3; ky++)
#pragma unroll
                for (int kx = 0; kx < 3; kx++)
                    v[ky * 3 + kx] = sin_s[ci][(py + ky) * 18 + px + kx];
#pragma unroll
            for (int co = 0; co < 8; co++) {
                float agv = accg[co], abv = accb[co];
#pragma unroll
                for (int k = 0; k < 9; k++) {
                    agv = fmaf(v[k], swg[co][ci][k], agv);
                    abv = fmaf(v[k], swb[co][ci][k], abv);
                }
                accg[co] = agv; accb[co] = abv;
            }
        }
        __syncthreads();
    }

    const float sum = g_stats[layer * 4 + b * 2 + 0];
    const float sumsq = g_stats[layer * 4 + b * 2 + 1];
    const float mean = sum * invN;
    const float rstd = rsqrtf(sumsq * invN - mean * mean + LNEPS);

    const int p = (ty0 + py) * RH + tx0 + px;
#pragma unroll
    for (int co = 0; co < 8; co++) {
        int c = co0 + co;
        float gv = accg[co] + bg[c];
        float be = accb[co] + bb[c];
        float xv = x[((size_t)b * nf + c) * P2 + p];
        act[((size_t)b * nf + c) * P2 + p] = fmaf((xv - mean) * rstd, 1.f + gv, be);
    }
}

// ---------------- 1x1 conv + softplus ---------------------------------------
__device__ __forceinline__ float softplus_f(float z) {
    return fmaxf(z, 0.f) + log1pf(expf(-fabsf(z)));
}

// layer0 1x1: channel-split partials. grid (9, 12, 2), 256 thr.
__global__ void conv1x1_part_k(const float* __restrict__ w0) {
    const int p = blockIdx.x * 256 + threadIdx.x;
    const int ck = blockIdx.y, b = blockIdx.z;
    const int c0 = ck * 256;
    __shared__ float ws[8][256];
    for (int i = threadIdx.x; i < 8 * 256; i += 256)
        ws[i >> 8][i & 255] = w0[(size_t)(i >> 8) * CM + c0 + (i & 255)];
    __syncthreads();
    float acc[8] = {0, 0, 0, 0, 0, 0, 0, 0};
    const float* ap = g_act0 + ((size_t)b * CM + c0) * P2 + p;
#pragma unroll 4
    for (int c = 0; c < 256; c++) {
        float v = ap[(size_t)c * P2];
#pragma unroll
        for (int j = 0; j < 8; j++) acc[j] = fmaf(ws[j][c], v, acc[j]);
    }
#pragma unroll
    for (int j = 0; j < 8; j++)
        g_red[((b * 12 + ck) * 8 + j) * P2 + p] = acc[j];
}

__global__ void reduce_x1_k(const float* __restrict__ bias0) {
    const int p = blockIdx.x * 256 + threadIdx.x;
    const int b = blockIdx.y;
#pragma unroll
    for (int j = 0; j < 8; j++) {
        float s = 0.f;
#pragma unroll
        for (int k = 0; k < 12; k++) s += g_red[((b * 12 + k) * 8 + j) * P2 + p];
        g_x1[(b * 8 + j) * P2 + p] = softplus_f(s + bias0[j]);
    }
}

template <int COUT>
__global__ void conv1x1_softplus_k(const float* __restrict__ act,
                                   const float* __restrict__ w,
                                   const float* __restrict__ bias,
                                   float* __restrict__ out, int Cin) {
    const int p = blockIdx.x * blockDim.x + threadIdx.x;
    const int b = blockIdx.y;
    float acc[COUT];
#pragma unroll
    for (int j = 0; j < COUT; j++) acc[j] = 0.f;
    const float* ab = act + (size_t)b * Cin * P2 + p;
#pragma unroll 4
    for (int c = 0; c < Cin; c++) {
        float v = ab[(size_t)c * P2];
#pragma unroll
        for (int j = 0; j < COUT; j++)
            acc[j] = fmaf(__ldg(&w[(size_t)j * Cin + c]), v, acc[j]);
    }
#pragma unroll
    for (int j = 0; j < COUT; j++)
        out[((size_t)b * COUT + j) * P2 + p] = softplus_f(acc[j] + bias[j]);
}

// ---------------------------------------------------------------------------
static float* sym_ptr(const void* sym) {
    void* p = nullptr;
    cudaGetSymbolAddress(&p, sym);
    return (float*)p;
}

extern "C" void kernel_launch(void* const* d_in, const int* in_sizes, int n_in,
                              void* d_out, int out_size) {
    const float* x_main = (const float*)d_in[0];
    const float* f_sem = (const float*)d_in[1];
    const int* segmap = (const int*)d_in[2];
    const float* ws[3] = {(const float*)d_in[3], (const float*)d_in[9], (const float*)d_in[15]};
    const float* bs[3] = {(const float*)d_in[4], (const float*)d_in[10], (const float*)d_in[16]};
    const float* wg[3] = {(const float*)d_in[5], (const float*)d_in[11], (const float*)d_in[17]};
    const float* bg[3] = {(const float*)d_in[6], (const float*)d_in[12], (const float*)d_in[18]};
    const float* wb[3] = {(const float*)d_in[7], (const float*)d_in[13], (const float*)d_in[19]};
    const float* bb[3] = {(const float*)d_in[8], (const float*)d_in[14], (const float*)d_in[20]};
    const float* w1x[3] = {(const float*)d_in[21], (const float*)d_in[23], (const float*)d_in[25]};
    const float* b1x[3] = {(const float*)d_in[22], (const float*)d_in[24], (const float*)d_in[26]};
    float* out = (float*)d_out;

    float* p_h = sym_ptr(g_h);
    float* p_x1 = sym_ptr(g_x1);
    float* p_act1 = sym_ptr(g_act1);
    float* p_x2 = sym_ptr(g_x2);
    float* p_act2 = sym_ptr(g_act2);

    zero_stats_k<<<1, 32>>>();
    seg_means_k<<<dim3(NSEG, NB), 256>>>(f_sem, segmap);
    paint_resize_k<<<dim3(RH, RH, NB), 256>>>(segmap);

    shconv_k<<<dim3(9, HID / 16, 6), 128>>>(ws[0], ws[1], ws[2], bs[0], bs[1], bs[2]);

    // ---- layer 0 ----
    ln_stats4_k<<<dim3(256, NB), 256>>>((const float4*)x_main, CM * P2 / 4, 0);
    spade0_k<<<dim3(9, CM / 16, NB), 128>>>(wg[0], bg[0], wb[0], bb[0], x_main);
    conv1x1_part_k<<<dim3(9, 12, NB), 256>>>(w1x[0]);
    reduce_x1_k<<<dim3(9, NB), 256>>>(b1x[0]);

    // ---- layer 1 ----
    ln_stats4_k<<<dim3(2, NB), 256>>>((const float4*)p_x1, 8 * P2 / 4, 1);
    spade_apply_k<<<dim3(9, 1, NB), 256>>>(p_h + (size_t)1 * NB * HID * P2,
                                           wg[1], bg[1], wb[1], bb[1],
                                           p_x1, p_act1, 1, 1.f / (8 * P2));
    conv1x1_softplus_k<16><<<dim3(9, NB), 256>>>(p_act1, w1x[1], b1x[1], p_x2, 8);

    // ---- layer 2 ----
    ln_stats4_k<<<dim3(2, NB), 256>>>((const float4*)p_x2, 16 * P2 / 4, 2);
    spade_apply_k<<<dim3(9, 2, NB), 256>>>(p_h + (size_t)2 * NB * HID * P2,
                                           wg[2], bg[2], wb[2], bb[2],
                                           p_x2, p_act2, 2, 1.f / (16 * P2));
    conv1x1_softplus_k<1><<<dim3(9, NB), 256>>>(p_act2, w1x[2], b1x[2], out, 16);
}